// round 14
// baseline (speedup 1.0000x reference)
#include <cuda_runtime.h>
#include <cuda_fp16.h>
#include <cstdint>

#define DI __device__ __forceinline__

// scratch (device globals; no allocation allowed; referenced ONLY from device code)
static __device__ __half  g_wo2[512 * 32];                // w_o packed [d8][n][4xhalf2]
static __device__ float   g_wo1[4 * 32 * 512];            // w_o k-split partials [ks][n][d]
static __device__ float   g_epart[4u * 32u * 512u * 32u]; // e partials [dc][b][l][n]
static __device__ float   g_alpha[32u * 512u * 32u];      // alpha [b][l][n]
static __device__ float   g_part[32 * 4 * 32 * 512];      // vf partials [b][lc][n][d]

DI __half2 tanh2(__half2 x) {
    uint32_t r, xi = *(uint32_t*)&x;
    asm("tanh.approx.f16x2 %0, %1;" : "=r"(r) : "r"(xi));
    return *(__half2*)&r;
}
DI uint32_t smem_u32(const void* p) { return (uint32_t)__cvta_generic_to_shared(p); }
DI void ldsm4(uint32_t r[4], uint32_t addr) {
    asm volatile("ldmatrix.sync.aligned.m8n8.x4.shared.b16 {%0,%1,%2,%3}, [%4];"
                 : "=r"(r[0]), "=r"(r[1]), "=r"(r[2]), "=r"(r[3]) : "r"(addr));
}
DI void ldsm4t(uint32_t r[4], uint32_t addr) {
    asm volatile("ldmatrix.sync.aligned.m8n8.x4.trans.shared.b16 {%0,%1,%2,%3}, [%4];"
                 : "=r"(r[0]), "=r"(r[1]), "=r"(r[2]), "=r"(r[3]) : "r"(addr));
}
DI void mma16(float c[4], const uint32_t a[4], uint32_t b0, uint32_t b1) {
    asm volatile("mma.sync.aligned.m16n8k16.row.col.f32.f16.f16.f32 "
                 "{%0,%1,%2,%3}, {%4,%5,%6,%7}, {%8,%9}, {%0,%1,%2,%3};"
                 : "+f"(c[0]), "+f"(c[1]), "+f"(c[2]), "+f"(c[3])
                 : "r"(a[0]), "r"(a[1]), "r"(a[2]), "r"(a[3]), "r"(b0), "r"(b1));
}

// ---------- K0: no-op slot shifter (k23 stays in the ncu 4th-launch capture slot) ----------
__global__ void k0_nop() {}

// ---------- K1a: w_o partials = emb @ Wo over a 128-k slice ----------
__global__ __launch_bounds__(128)
void k1a_wo(const float* __restrict__ emb, const float* __restrict__ Wo) {
    const int ks = blockIdx.x, n = blockIdx.y, tid = threadIdx.x;
    const int d0 = tid * 4;
    __shared__ float es[128];
    es[tid] = emb[n * 512 + ks * 128 + tid];
    __syncthreads();
    float4 a = make_float4(0.f, 0.f, 0.f, 0.f);
    const float* w = Wo + (size_t)(ks * 128) * 512 + d0;
#pragma unroll 8
    for (int k = 0; k < 128; k++) {
        float e = es[k];
        float4 wv = *(const float4*)(w + (size_t)k * 512);
        a.x = fmaf(e, wv.x, a.x); a.y = fmaf(e, wv.y, a.y);
        a.z = fmaf(e, wv.z, a.z); a.w = fmaf(e, wv.w, a.w);
    }
    *(float4*)(g_wo1 + ((size_t)(ks * 32 + n)) * 512 + d0) = a;
}

// ---------- K1b: reduce 4 k-split partials + bias, pack half [d8][n][4*half2] ----------
__global__ __launch_bounds__(256)
void k1b_wo(const float* __restrict__ Wob) {
    int idx = blockIdx.x * 256 + threadIdx.x;  // 4096
    int n = idx >> 7, d4 = idx & 127, d0 = d4 * 4;
    float4 a = make_float4(Wob[d0], Wob[d0+1], Wob[d0+2], Wob[d0+3]);
#pragma unroll
    for (int ks = 0; ks < 4; ks++) {
        float4 p = *(const float4*)(g_wo1 + ((size_t)(ks * 32 + n)) * 512 + d0);
        a.x += p.x; a.y += p.y; a.z += p.z; a.w += p.w;
    }
    __half2 h01 = __floats2half2_rn(a.x, a.y);
    __half2 h23 = __floats2half2_rn(a.z, a.w);
    int d8 = d4 >> 1;
    uint2 v = make_uint2(*(uint32_t*)&h01, *(uint32_t*)&h23);
    ((uint2*)g_wo2)[d8 * 64 + n * 2 + (d4 & 1)] = v;
}

// ---------- K23: w_v = inp @ Wv + b, f16 mma + XOR-swizzled ldmatrix tiles, fused tanh ----------
// A stage: 128 rows x 32B, phys = (r>>2)*128 + (((r&3)*2+j)^((r>>2)&7))*16  (+8B sub)
// B stage: 16 k x 256B,   phys = k*256 + ((c^(k&7)))*16                     (+8B sub)
#define VST 68
#define STAGE_B 4096
__global__ __launch_bounds__(256, 2)
void k23_gemm_tanh(const float* __restrict__ A, const float* __restrict__ B,
                   const float* __restrict__ bias, const float* __restrict__ We) {
    // union: mainloop A[3]+B[3] = 24576B  vs  epilogue v_s 34816 | wo_s 8192 | we_s 512
    __shared__ __align__(128) char sraw[43520];
    char*     Abase = sraw;                     // 3 A stages
    char*     Bbase = sraw + 3 * STAGE_B;       // 3 B stages
    uint32_t* v_s  = (uint32_t*)sraw;           // [128*VST] half2 bits
    uint4*    wo_s = (uint4*)(sraw + 34816);    // [16*32]
    float*    we_s = (float*)(sraw + 43008);    // [128]
    __shared__ float bias_s[128];

    const int tid = threadIdx.x;
    const int bm0 = blockIdx.y * 128, bn0 = blockIdx.x * 128;
    const int warp = tid >> 5, lane = tid & 31;
    const int wm = warp >> 2, wn = warp & 3;
    const int g = lane >> 2, tig = lane & 3;
    if (tid < 128) bias_s[tid] = bias[bn0 + tid];

    // staging geometry: per thread 2 A-chunks + 2 B-chunks of 8B (after cvt)
    int ar[2], aoff[2], bk[2], boff[2];
#pragma unroll
    for (int i = 0; i < 2; i++) {
        int c = tid + 256 * i;
        ar[i] = c >> 2;
        int ak = c & 3;                          // 8B chunk within 32B row
        int aj = ak >> 1, asub = ak & 1;
        int aslot = ((ar[i] & 3) * 2 + aj) ^ ((ar[i] >> 2) & 7);
        aoff[i] = (ar[i] >> 2) * 128 + aslot * 16 + asub * 8;
        bk[i] = c >> 5;
        int bn = c & 31;                         // 8B chunk within 256B row
        int bc = bn >> 1, bsub = bn & 1;
        int bslot = bc ^ (bk[i] & 7);
        boff[i] = bk[i] * 256 + bslot * 16 + bsub * 8;
    }
    float4 pa[2], pb[2];
    auto ldg = [&](int k0) {
#pragma unroll
        for (int i = 0; i < 2; i++) {
            int c = tid + 256 * i;
            pa[i] = *(const float4*)(A + (size_t)(bm0 + ar[i]) * 512 + k0 + (c & 3) * 4);
            pb[i] = *(const float4*)(B + (size_t)(k0 + bk[i]) * 512 + bn0 + (c & 31) * 4);
        }
    };
    auto sts = [&](int buf) {
#pragma unroll
        for (int i = 0; i < 2; i++) {
            __half2 a01 = __floats2half2_rn(pa[i].x, pa[i].y);
            __half2 a23 = __floats2half2_rn(pa[i].z, pa[i].w);
            *(uint2*)(Abase + buf * STAGE_B + aoff[i]) =
                make_uint2(*(uint32_t*)&a01, *(uint32_t*)&a23);
            __half2 b01 = __floats2half2_rn(pb[i].x, pb[i].y);
            __half2 b23 = __floats2half2_rn(pb[i].z, pb[i].w);
            *(uint2*)(Bbase + buf * STAGE_B + boff[i]) =
                make_uint2(*(uint32_t*)&b01, *(uint32_t*)&b23);
        }
    };

    float c[4][4][4];
#pragma unroll
    for (int mi = 0; mi < 4; mi++)
#pragma unroll
        for (int ni = 0; ni < 4; ni++)
#pragma unroll
            for (int j = 0; j < 4; j++) c[mi][ni][j] = 0.f;

    // ldmatrix lane addresses (swizzled, within-stage bytes)
    uint32_t a_addr[4], b_addr[2];
    {
        const uint32_t AhU = smem_u32(Abase), BhU = smem_u32(Bbase);
        int j = lane >> 4;
#pragma unroll
        for (int mi = 0; mi < 4; mi++) {
            int r = wm * 64 + mi * 16 + (lane & 15);
            int slot = ((r & 3) * 2 + j) ^ ((r >> 2) & 7);
            a_addr[mi] = AhU + (uint32_t)((r >> 2) * 128 + slot * 16);
        }
#pragma unroll
        for (int jj = 0; jj < 2; jj++) {
            int k = lane & 15;
            int cc = wn * 4 + (lane >> 4) + 2 * jj;
            int slot = cc ^ (k & 7);
            b_addr[jj] = BhU + (uint32_t)(k * 256 + slot * 16);
        }
    }

    // prologue: stage 0 stored, stage 1 loaded into regs
    ldg(0); sts(0); ldg(16);
    int buf = 0;
    for (int s = 0; s < 32; s++) {
        __syncthreads();
        int nb = buf + 1; if (nb == 3) nb = 0;
        if (s + 1 < 32) sts(nb);
        if (s + 2 < 32) ldg((s + 2) * 16);
        uint32_t boffs = (uint32_t)buf * STAGE_B;
        uint32_t a[4][4], b2[2][4];
#pragma unroll
        for (int mi = 0; mi < 4; mi++) ldsm4(a[mi], a_addr[mi] + boffs);
#pragma unroll
        for (int j = 0; j < 2; j++) ldsm4t(b2[j], b_addr[j] + boffs);
#pragma unroll
        for (int mi = 0; mi < 4; mi++)
#pragma unroll
            for (int ni = 0; ni < 4; ni++)
                mma16(c[mi][ni], a[mi], b2[ni >> 1][(ni & 1) * 2], b2[ni >> 1][(ni & 1) * 2 + 1]);
        buf = nb;
    }
    __syncthreads();   // all warps done reading tiles before v_s alias writes

    // epilogue phase 1: stage wo/We tiles + fragments (half2) into smem
    {
        const uint4* wog = (const uint4*)g_wo2;
        int d8base = bn0 >> 3;
        wo_s[tid]       = wog[(d8base + (tid >> 5)) * 32 + lane];
        wo_s[tid + 256] = wog[(d8base + 8 + (tid >> 5)) * 32 + lane];
        if (tid < 32) ((float4*)we_s)[tid] = ((const float4*)(We + bn0))[tid];
    }
#pragma unroll
    for (int mi = 0; mi < 4; mi++) {
        int r = wm * 64 + mi * 16 + g;
#pragma unroll
        for (int ni = 0; ni < 4; ni++) {
            int colL = wn * 32 + ni * 8 + 2 * tig;
            float b0 = bias_s[colL], b1 = bias_s[colL + 1];
            int d2 = wn * 16 + ni * 4 + tig;
            __half2 h0 = __floats2half2_rn(c[mi][ni][0] + b0, c[mi][ni][1] + b1);
            __half2 h1 = __floats2half2_rn(c[mi][ni][2] + b0, c[mi][ni][3] + b1);
            v_s[r * VST + d2]       = *(uint32_t*)&h0;
            v_s[(r + 8) * VST + d2] = *(uint32_t*)&h1;
        }
    }
    __syncthreads();

    // epilogue phase 2: e_partial[l][n] over this block's 128 d
    const int bq = bm0 >> 9;
    const int l0 = bm0 & 511;
    const int n = lane;
    float* ep = g_epart + (((size_t)blockIdx.x * 32 + bq) * 512 + l0) * 32;
#pragma unroll 2
    for (int li = 0; li < 16; li++) {
        int l = warp * 16 + li;
        float acc = 0.f;
#pragma unroll 4
        for (int d8 = 0; d8 < 16; d8++) {
            uint4 wo = wo_s[d8 * 32 + n];
            uint4 wv = *(const uint4*)&v_s[l * VST + d8 * 4];
            float4 we0 = ((const float4*)we_s)[d8 * 2];
            float4 we1 = ((const float4*)we_s)[d8 * 2 + 1];
            const __half2* wop = (const __half2*)&wo;
            const __half2* wvp = (const __half2*)&wv;
            float2 t0 = __half22float2(tanh2(__hadd2(wop[0], wvp[0])));
            float2 t1 = __half22float2(tanh2(__hadd2(wop[1], wvp[1])));
            float2 t2 = __half22float2(tanh2(__hadd2(wop[2], wvp[2])));
            float2 t3 = __half22float2(tanh2(__hadd2(wop[3], wvp[3])));
            acc = fmaf(t0.x, we0.x, acc); acc = fmaf(t0.y, we0.y, acc);
            acc = fmaf(t1.x, we0.z, acc); acc = fmaf(t1.y, we0.w, acc);
            acc = fmaf(t2.x, we1.x, acc); acc = fmaf(t2.y, we1.y, acc);
            acc = fmaf(t3.x, we1.z, acc); acc = fmaf(t3.y, we1.w, acc);
        }
        ep[(size_t)l * 32 + n] = acc;
    }
}

// ---------- K4: e = sum of 4 d-chunk partials, softmax over l, alpha [b][l][n] ----------
__global__ __launch_bounds__(512)
void k4_softmax() {
    const int b = blockIdx.x, tid = threadIdx.x;
    const int w = tid >> 5, n = tid & 31;
    const float* e0 = g_epart + ((size_t)b * 512) * 32;
    const size_t dstr = (size_t)32 * 512 * 32;
    __shared__ float red[16][32];
    float ev[32];
    float m = -1e30f;
#pragma unroll 4
    for (int i = 0; i < 32; i++) {
        size_t idx = (size_t)(w * 32 + i) * 32 + n;
        float e = (e0[idx] + e0[idx + dstr]) + (e0[idx + 2 * dstr] + e0[idx + 3 * dstr]);
        ev[i] = e; m = fmaxf(m, e);
    }
    red[w][n] = m; __syncthreads();
#pragma unroll
    for (int ww = 0; ww < 16; ww++) m = fmaxf(m, red[ww][n]);
    __syncthreads();
    float s = 0.f;
#pragma unroll 4
    for (int i = 0; i < 32; i++) { ev[i] = __expf(ev[i] - m); s += ev[i]; }
    red[w][n] = s; __syncthreads();
    s = 0.f;
#pragma unroll
    for (int ww = 0; ww < 16; ww++) s += red[ww][n];
    float inv = 1.f / s;
    float* a = g_alpha + ((size_t)b * 512) * 32;
#pragma unroll 4
    for (int i = 0; i < 32; i++) a[(size_t)(w * 32 + i) * 32 + n] = ev[i] * inv;
}

// ---------- K5a: vf partials, 128-l chunks, n split in halves of 16 ----------
__global__ __launch_bounds__(128)
void k5a_vf(const float* __restrict__ inp) {
    const int b = blockIdx.x, tid = threadIdx.x;
    const int d = blockIdx.y * 128 + tid;
    const int lc = blockIdx.z >> 1, nh = blockIdx.z & 1;
    const int lc0 = lc * 128, n0 = nh * 16;
    __shared__ float a_s[128][16];
    {
        const float* ga = g_alpha + ((size_t)b * 512 + lc0) * 32 + n0;
#pragma unroll
        for (int i = 0; i < 4; i++) {
            int idx = tid + 128 * i;
            int l = idx >> 2, nf = idx & 3;
            ((float4*)a_s[l])[nf] = *(const float4*)(ga + (size_t)l * 32 + nf * 4);
        }
    }
    __syncthreads();
    float acc[16];
#pragma unroll
    for (int n = 0; n < 16; n++) acc[n] = 0.f;
    const float* ib = inp + ((size_t)b * 512 + lc0) * 512 + d;
#pragma unroll 4
    for (int l = 0; l < 128; l++) {
        float x = ib[(size_t)l * 512];
        const float4* ar = (const float4*)a_s[l];
#pragma unroll
        for (int n4 = 0; n4 < 4; n4++) {
            float4 a4 = ar[n4];
            acc[n4 * 4 + 0] = fmaf(a4.x, x, acc[n4 * 4 + 0]);
            acc[n4 * 4 + 1] = fmaf(a4.y, x, acc[n4 * 4 + 1]);
            acc[n4 * 4 + 2] = fmaf(a4.z, x, acc[n4 * 4 + 2]);
            acc[n4 * 4 + 3] = fmaf(a4.w, x, acc[n4 * 4 + 3]);
        }
    }
#pragma unroll
    for (int n = 0; n < 16; n++)
        g_part[(((size_t)b * 4 + lc) * 32 + n0 + n) * 512 + d] = acc[n];
}

// ---------- K6: reduce partials -> vf (written to out) AND logits = vf @ Wc + b ----------
__global__ __launch_bounds__(256)
void k6_logits(const float* __restrict__ Wc, const float* __restrict__ Wcb,
               float* __restrict__ vf, float* __restrict__ out) {
    const int tid = threadIdx.x;
    const int w = tid >> 5, lane = tid & 31;
    const int row0 = blockIdx.x * 8;
    __shared__ float v_s[8][512];
    {
        const float4* p = (const float4*)g_part;
#pragma unroll
        for (int i = 0; i < 4; i++) {
            int idx = tid + 256 * i;                 // local f4 idx 0..1023
            int gidx = row0 * 128 + idx;             // global f4 idx
            int row = gidx >> 7, d4 = gidx & 127;
            int b = row >> 5, n = row & 31;
            size_t base = (size_t)((b * 4) * 32 + n) * 128 + d4;
            const size_t lstr = (size_t)32 * 128;
            float4 s0 = p[base], s1 = p[base + lstr];
            float4 s2 = p[base + 2 * lstr], s3 = p[base + 3 * lstr];
            float4 o;
            o.x = (s0.x + s1.x) + (s2.x + s3.x);
            o.y = (s0.y + s1.y) + (s2.y + s3.y);
            o.z = (s0.z + s1.z) + (s2.z + s3.z);
            o.w = (s0.w + s1.w) + (s2.w + s3.w);
            ((float4*)v_s)[idx] = o;
            ((float4*)vf)[gidx] = o;
        }
    }
    __syncthreads();
    const int row = row0 + w;
    const float* vr = v_s[w];
    float a0 = 0.f, a1 = 0.f, a2 = 0.f, a3 = 0.f;
    const int c0 = lane, c1 = lane + 32, c2 = lane + 64;
#pragma unroll 8
    for (int k = 0; k < 512; k++) {
        float v = vr[k];
        const float* wr = Wc + (size_t)k * 97;
        a0 = fmaf(v, wr[c0], a0);
        a1 = fmaf(v, wr[c1], a1);
        a2 = fmaf(v, wr[c2], a2);
        if (lane == 0) a3 = fmaf(v, wr[96], a3);
    }
    float* orow = out + (size_t)row * 97;
    orow[c0] = a0 + Wcb[c0];
    orow[c1] = a1 + Wcb[c1];
    orow[c2] = a2 + Wcb[c2];
    if (lane == 0) orow[96] = a3 + Wcb[96];
}

extern "C" void kernel_launch(void* const* d_in, const int* in_sizes, int n_in,
                              void* d_out, int out_size) {
    const float* inp  = (const float*)d_in[0];
    const float* emb  = (const float*)d_in[1];
    const float* Wo_w = (const float*)d_in[2];
    const float* Wo_b = (const float*)d_in[3];
    const float* Wv_w = (const float*)d_in[4];
    const float* Wv_b = (const float*)d_in[5];
    const float* We_w = (const float*)d_in[6];
    const float* Wc_w = (const float*)d_in[8];
    const float* Wc_b = (const float*)d_in[9];
    float* out = (float*)d_out;
    float* vf = out;                         // (32*32, 512)
    float* logits = out + 32 * 32 * 512;     // (32*32, 97)

    k0_nop<<<1, 32>>>();                               // keep k23 in ncu's 4th slot
    k1a_wo<<<dim3(4, 32), 128>>>(emb, Wo_w);
    k1b_wo<<<16, 256>>>(Wo_b);
    k23_gemm_tanh<<<dim3(4, 128), 256>>>(inp, Wv_w, Wv_b, We_w);
    k4_softmax<<<32, 512>>>();
    k5a_vf<<<dim3(32, 4, 8), 128>>>(inp);
    k6_logits<<<128, 256>>>(Wc_w, Wc_b, vf, logits);
}

// round 15
// speedup vs baseline: 1.0571x; 1.0571x over previous
#include <cuda_runtime.h>
#include <cuda_fp16.h>
#include <cstdint>

#define DI __device__ __forceinline__

// scratch (device globals; no allocation allowed; referenced ONLY from device code)
static __device__ __half  g_wo2[512 * 32];                // w_o packed [d8][n][4xhalf2]
static __device__ float   g_wo1[4 * 32 * 512];            // w_o k-split partials [ks][n][d]
static __device__ float   g_epart[4u * 32u * 512u * 32u]; // e partials [dc][b][l][n]
static __device__ float   g_alpha[32u * 512u * 32u];      // alpha [b][l][n]
static __device__ float   g_part[32 * 4 * 32 * 512];      // vf partials [b][lc][n][d]

DI __half2 tanh2(__half2 x) {
    uint32_t r, xi = *(uint32_t*)&x;
    asm("tanh.approx.f16x2 %0, %1;" : "=r"(r) : "r"(xi));
    return *(__half2*)&r;
}
DI uint32_t smem_u32(const void* p) { return (uint32_t)__cvta_generic_to_shared(p); }
DI void ldsm4(uint32_t r[4], uint32_t addr) {
    asm volatile("ldmatrix.sync.aligned.m8n8.x4.shared.b16 {%0,%1,%2,%3}, [%4];"
                 : "=r"(r[0]), "=r"(r[1]), "=r"(r[2]), "=r"(r[3]) : "r"(addr));
}
DI void ldsm4t(uint32_t r[4], uint32_t addr) {
    asm volatile("ldmatrix.sync.aligned.m8n8.x4.trans.shared.b16 {%0,%1,%2,%3}, [%4];"
                 : "=r"(r[0]), "=r"(r[1]), "=r"(r[2]), "=r"(r[3]) : "r"(addr));
}
DI void mma16(float c[4], const uint32_t a[4], uint32_t b0, uint32_t b1) {
    asm volatile("mma.sync.aligned.m16n8k16.row.col.f32.f16.f16.f32 "
                 "{%0,%1,%2,%3}, {%4,%5,%6,%7}, {%8,%9}, {%0,%1,%2,%3};"
                 : "+f"(c[0]), "+f"(c[1]), "+f"(c[2]), "+f"(c[3])
                 : "r"(a[0]), "r"(a[1]), "r"(a[2]), "r"(a[3]), "r"(b0), "r"(b1));
}

// ---------- K0: no-op slot shifter (k23 stays in the ncu 4th-launch capture slot) ----------
__global__ void k0_nop() {}

// ---------- K1a: w_o partials = emb @ Wo over a 128-k slice ----------
__global__ __launch_bounds__(128)
void k1a_wo(const float* __restrict__ emb, const float* __restrict__ Wo) {
    const int ks = blockIdx.x, n = blockIdx.y, tid = threadIdx.x;
    const int d0 = tid * 4;
    __shared__ float es[128];
    es[tid] = emb[n * 512 + ks * 128 + tid];
    __syncthreads();
    float4 a = make_float4(0.f, 0.f, 0.f, 0.f);
    const float* w = Wo + (size_t)(ks * 128) * 512 + d0;
#pragma unroll 8
    for (int k = 0; k < 128; k++) {
        float e = es[k];
        float4 wv = *(const float4*)(w + (size_t)k * 512);
        a.x = fmaf(e, wv.x, a.x); a.y = fmaf(e, wv.y, a.y);
        a.z = fmaf(e, wv.z, a.z); a.w = fmaf(e, wv.w, a.w);
    }
    *(float4*)(g_wo1 + ((size_t)(ks * 32 + n)) * 512 + d0) = a;
}

// ---------- K1b: reduce 4 k-split partials + bias, pack half [d8][n][4*half2] ----------
__global__ __launch_bounds__(256)
void k1b_wo(const float* __restrict__ Wob) {
    int idx = blockIdx.x * 256 + threadIdx.x;  // 4096
    int n = idx >> 7, d4 = idx & 127, d0 = d4 * 4;
    float4 a = make_float4(Wob[d0], Wob[d0+1], Wob[d0+2], Wob[d0+3]);
#pragma unroll
    for (int ks = 0; ks < 4; ks++) {
        float4 p = *(const float4*)(g_wo1 + ((size_t)(ks * 32 + n)) * 512 + d0);
        a.x += p.x; a.y += p.y; a.z += p.z; a.w += p.w;
    }
    __half2 h01 = __floats2half2_rn(a.x, a.y);
    __half2 h23 = __floats2half2_rn(a.z, a.w);
    int d8 = d4 >> 1;
    uint2 v = make_uint2(*(uint32_t*)&h01, *(uint32_t*)&h23);
    ((uint2*)g_wo2)[d8 * 64 + n * 2 + (d4 & 1)] = v;
}

// ---------- K23: w_v = inp @ Wv + b, f16 mma + XOR-swizzled ldmatrix tiles, fused tanh ----------
#define VST 68
#define STAGE_B 4096
__global__ __launch_bounds__(256, 2)
void k23_gemm_tanh(const float* __restrict__ A, const float* __restrict__ B,
                   const float* __restrict__ bias, const float* __restrict__ We) {
    // union: mainloop A[3]+B[3] = 24576B  vs  epilogue v_s 34816 | wo_s 8192 | we_s 512
    __shared__ __align__(128) char sraw[43520];
    char*     Abase = sraw;                     // 3 A stages
    char*     Bbase = sraw + 3 * STAGE_B;       // 3 B stages
    uint32_t* v_s  = (uint32_t*)sraw;           // [128*VST] half2 bits
    uint4*    wo_s = (uint4*)(sraw + 34816);    // [16*32]
    float*    we_s = (float*)(sraw + 43008);    // [128]
    __shared__ float bias_s[128];

    const int tid = threadIdx.x;
    const int bm0 = blockIdx.y * 128, bn0 = blockIdx.x * 128;
    const int warp = tid >> 5, lane = tid & 31;
    const int wm = warp >> 2, wn = warp & 3;
    const int g = lane >> 2, tig = lane & 3;
    if (tid < 128) bias_s[tid] = bias[bn0 + tid];

    // staging geometry: per thread 2 A-chunks + 2 B-chunks of 8B (after cvt)
    int ar[2], aoff[2], bk[2], boff[2];
#pragma unroll
    for (int i = 0; i < 2; i++) {
        int c = tid + 256 * i;
        ar[i] = c >> 2;
        int ak = c & 3;
        int aj = ak >> 1, asub = ak & 1;
        int aslot = ((ar[i] & 3) * 2 + aj) ^ ((ar[i] >> 2) & 7);
        aoff[i] = (ar[i] >> 2) * 128 + aslot * 16 + asub * 8;
        bk[i] = c >> 5;
        int bn = c & 31;
        int bc = bn >> 1, bsub = bn & 1;
        int bslot = bc ^ (bk[i] & 7);
        boff[i] = bk[i] * 256 + bslot * 16 + bsub * 8;
    }
    float4 pa[2], pb[2];
    auto ldg = [&](int k0) {
#pragma unroll
        for (int i = 0; i < 2; i++) {
            int c = tid + 256 * i;
            pa[i] = *(const float4*)(A + (size_t)(bm0 + ar[i]) * 512 + k0 + (c & 3) * 4);
            pb[i] = *(const float4*)(B + (size_t)(k0 + bk[i]) * 512 + bn0 + (c & 31) * 4);
        }
    };
    auto sts = [&](int buf) {
#pragma unroll
        for (int i = 0; i < 2; i++) {
            __half2 a01 = __floats2half2_rn(pa[i].x, pa[i].y);
            __half2 a23 = __floats2half2_rn(pa[i].z, pa[i].w);
            *(uint2*)(Abase + buf * STAGE_B + aoff[i]) =
                make_uint2(*(uint32_t*)&a01, *(uint32_t*)&a23);
            __half2 b01 = __floats2half2_rn(pb[i].x, pb[i].y);
            __half2 b23 = __floats2half2_rn(pb[i].z, pb[i].w);
            *(uint2*)(Bbase + buf * STAGE_B + boff[i]) =
                make_uint2(*(uint32_t*)&b01, *(uint32_t*)&b23);
        }
    };

    float c[4][4][4];
#pragma unroll
    for (int mi = 0; mi < 4; mi++)
#pragma unroll
        for (int ni = 0; ni < 4; ni++)
#pragma unroll
            for (int j = 0; j < 4; j++) c[mi][ni][j] = 0.f;

    // ldmatrix lane addresses (swizzled, within-stage bytes)
    uint32_t a_addr[4], b_addr[2];
    {
        const uint32_t AhU = smem_u32(Abase), BhU = smem_u32(Bbase);
        int j = lane >> 4;
#pragma unroll
        for (int mi = 0; mi < 4; mi++) {
            int r = wm * 64 + mi * 16 + (lane & 15);
            int slot = ((r & 3) * 2 + j) ^ ((r >> 2) & 7);
            a_addr[mi] = AhU + (uint32_t)((r >> 2) * 128 + slot * 16);
        }
#pragma unroll
        for (int jj = 0; jj < 2; jj++) {
            int k = lane & 15;
            int cc = wn * 4 + (lane >> 4) + 2 * jj;
            int slot = cc ^ (k & 7);
            b_addr[jj] = BhU + (uint32_t)(k * 256 + slot * 16);
        }
    }

    // prologue: stage 0 stored, stage 1 loaded into regs
    ldg(0); sts(0); ldg(16);
    int buf = 0;
    for (int s = 0; s < 32; s++) {
        __syncthreads();
        int nb = buf + 1; if (nb == 3) nb = 0;
        if (s + 1 < 32) sts(nb);
        if (s + 2 < 32) ldg((s + 2) * 16);
        uint32_t boffs = (uint32_t)buf * STAGE_B;
        uint32_t a[4][4], b2[2][4];
#pragma unroll
        for (int mi = 0; mi < 4; mi++) ldsm4(a[mi], a_addr[mi] + boffs);
#pragma unroll
        for (int j = 0; j < 2; j++) ldsm4t(b2[j], b_addr[j] + boffs);
#pragma unroll
        for (int mi = 0; mi < 4; mi++)
#pragma unroll
            for (int ni = 0; ni < 4; ni++)
                mma16(c[mi][ni], a[mi], b2[ni >> 1][(ni & 1) * 2], b2[ni >> 1][(ni & 1) * 2 + 1]);
        buf = nb;
    }
    __syncthreads();   // all warps done reading tiles before v_s alias writes

    // epilogue phase 1: stage wo/We tiles + fragments (half2) into smem
    {
        const uint4* wog = (const uint4*)g_wo2;
        int d8base = bn0 >> 3;
        wo_s[tid]       = wog[(d8base + (tid >> 5)) * 32 + lane];
        wo_s[tid + 256] = wog[(d8base + 8 + (tid >> 5)) * 32 + lane];
        if (tid < 32) ((float4*)we_s)[tid] = ((const float4*)(We + bn0))[tid];
    }
#pragma unroll
    for (int mi = 0; mi < 4; mi++) {
        int r = wm * 64 + mi * 16 + g;
#pragma unroll
        for (int ni = 0; ni < 4; ni++) {
            int colL = wn * 32 + ni * 8 + 2 * tig;
            float b0 = bias_s[colL], b1 = bias_s[colL + 1];
            int d2 = wn * 16 + ni * 4 + tig;
            __half2 h0 = __floats2half2_rn(c[mi][ni][0] + b0, c[mi][ni][1] + b1);
            __half2 h1 = __floats2half2_rn(c[mi][ni][2] + b0, c[mi][ni][3] + b1);
            v_s[r * VST + d2]       = *(uint32_t*)&h0;
            v_s[(r + 8) * VST + d2] = *(uint32_t*)&h1;
        }
    }
    __syncthreads();

    // epilogue phase 2: e_partial[l][n] — outer d8, wo/we hoisted, per-li accumulators.
    // Per-(l,n) summation order identical to previous rounds -> bit-identical results.
    const int bq = bm0 >> 9;
    const int l0 = bm0 & 511;
    const int n = lane;
    float acc[16];
#pragma unroll
    for (int li = 0; li < 16; li++) acc[li] = 0.f;
#pragma unroll 1
    for (int d8 = 0; d8 < 16; d8++) {
        uint4 wo = wo_s[d8 * 32 + n];                 // loaded once per d8 (16x reuse)
        float4 we0 = ((const float4*)we_s)[d8 * 2];
        float4 we1 = ((const float4*)we_s)[d8 * 2 + 1];
        const __half2* wop = (const __half2*)&wo;
#pragma unroll
        for (int li = 0; li < 16; li++) {
            int l = warp * 16 + li;
            uint4 wv = *(const uint4*)&v_s[l * VST + d8 * 4];   // broadcast (1 wf)
            const __half2* wvp = (const __half2*)&wv;
            float2 t0 = __half22float2(tanh2(__hadd2(wop[0], wvp[0])));
            float2 t1 = __half22float2(tanh2(__hadd2(wop[1], wvp[1])));
            float2 t2 = __half22float2(tanh2(__hadd2(wop[2], wvp[2])));
            float2 t3 = __half22float2(tanh2(__hadd2(wop[3], wvp[3])));
            float a0 = acc[li];
            a0 = fmaf(t0.x, we0.x, a0); a0 = fmaf(t0.y, we0.y, a0);
            a0 = fmaf(t1.x, we0.z, a0); a0 = fmaf(t1.y, we0.w, a0);
            a0 = fmaf(t2.x, we1.x, a0); a0 = fmaf(t2.y, we1.y, a0);
            a0 = fmaf(t3.x, we1.z, a0); a0 = fmaf(t3.y, we1.w, a0);
            acc[li] = a0;
        }
    }
    float* ep = g_epart + (((size_t)blockIdx.x * 32 + bq) * 512 + l0) * 32;
#pragma unroll
    for (int li = 0; li < 16; li++)
        ep[(size_t)(warp * 16 + li) * 32 + n] = acc[li];
}

// ---------- K4: e = sum of 4 d-chunk partials, softmax over l, alpha [b][l][n] ----------
__global__ __launch_bounds__(512)
void k4_softmax() {
    const int b = blockIdx.x, tid = threadIdx.x;
    const int w = tid >> 5, n = tid & 31;
    const float* e0 = g_epart + ((size_t)b * 512) * 32;
    const size_t dstr = (size_t)32 * 512 * 32;
    __shared__ float red[16][32];
    float ev[32];
    float m = -1e30f;
#pragma unroll 4
    for (int i = 0; i < 32; i++) {
        size_t idx = (size_t)(w * 32 + i) * 32 + n;
        float e = (e0[idx] + e0[idx + dstr]) + (e0[idx + 2 * dstr] + e0[idx + 3 * dstr]);
        ev[i] = e; m = fmaxf(m, e);
    }
    red[w][n] = m; __syncthreads();
#pragma unroll
    for (int ww = 0; ww < 16; ww++) m = fmaxf(m, red[ww][n]);
    __syncthreads();
    float s = 0.f;
#pragma unroll 4
    for (int i = 0; i < 32; i++) { ev[i] = __expf(ev[i] - m); s += ev[i]; }
    red[w][n] = s; __syncthreads();
    s = 0.f;
#pragma unroll
    for (int ww = 0; ww < 16; ww++) s += red[ww][n];
    float inv = 1.f / s;
    float* a = g_alpha + ((size_t)b * 512) * 32;
#pragma unroll 4
    for (int i = 0; i < 32; i++) a[(size_t)(w * 32 + i) * 32 + n] = ev[i] * inv;
}

// ---------- K5a: vf partials, 128-l chunks, n split in halves of 16 ----------
__global__ __launch_bounds__(128)
void k5a_vf(const float* __restrict__ inp) {
    const int b = blockIdx.x, tid = threadIdx.x;
    const int d = blockIdx.y * 128 + tid;
    const int lc = blockIdx.z >> 1, nh = blockIdx.z & 1;
    const int lc0 = lc * 128, n0 = nh * 16;
    __shared__ float a_s[128][16];
    {
        const float* ga = g_alpha + ((size_t)b * 512 + lc0) * 32 + n0;
#pragma unroll
        for (int i = 0; i < 4; i++) {
            int idx = tid + 128 * i;
            int l = idx >> 2, nf = idx & 3;
            ((float4*)a_s[l])[nf] = *(const float4*)(ga + (size_t)l * 32 + nf * 4);
        }
    }
    __syncthreads();
    float acc[16];
#pragma unroll
    for (int n = 0; n < 16; n++) acc[n] = 0.f;
    const float* ib = inp + ((size_t)b * 512 + lc0) * 512 + d;
#pragma unroll 4
    for (int l = 0; l < 128; l++) {
        float x = ib[(size_t)l * 512];
        const float4* ar = (const float4*)a_s[l];
#pragma unroll
        for (int n4 = 0; n4 < 4; n4++) {
            float4 a4 = ar[n4];
            acc[n4 * 4 + 0] = fmaf(a4.x, x, acc[n4 * 4 + 0]);
            acc[n4 * 4 + 1] = fmaf(a4.y, x, acc[n4 * 4 + 1]);
            acc[n4 * 4 + 2] = fmaf(a4.z, x, acc[n4 * 4 + 2]);
            acc[n4 * 4 + 3] = fmaf(a4.w, x, acc[n4 * 4 + 3]);
        }
    }
#pragma unroll
    for (int n = 0; n < 16; n++)
        g_part[(((size_t)b * 4 + lc) * 32 + n0 + n) * 512 + d] = acc[n];
}

// ---------- K6: reduce partials -> vf (written to out) AND logits = vf @ Wc + b ----------
__global__ __launch_bounds__(256)
void k6_logits(const float* __restrict__ Wc, const float* __restrict__ Wcb,
               float* __restrict__ vf, float* __restrict__ out) {
    const int tid = threadIdx.x;
    const int w = tid >> 5, lane = tid & 31;
    const int row0 = blockIdx.x * 8;
    __shared__ float v_s[8][512];
    {
        const float4* p = (const float4*)g_part;
#pragma unroll
        for (int i = 0; i < 4; i++) {
            int idx = tid + 256 * i;                 // local f4 idx 0..1023
            int gidx = row0 * 128 + idx;             // global f4 idx
            int row = gidx >> 7, d4 = gidx & 127;
            int b = row >> 5, n = row & 31;
            size_t base = (size_t)((b * 4) * 32 + n) * 128 + d4;
            const size_t lstr = (size_t)32 * 128;
            float4 s0 = p[base], s1 = p[base + lstr];
            float4 s2 = p[base + 2 * lstr], s3 = p[base + 3 * lstr];
            float4 o;
            o.x = (s0.x + s1.x) + (s2.x + s3.x);
            o.y = (s0.y + s1.y) + (s2.y + s3.y);
            o.z = (s0.z + s1.z) + (s2.z + s3.z);
            o.w = (s0.w + s1.w) + (s2.w + s3.w);
            ((float4*)v_s)[idx] = o;
            ((float4*)vf)[gidx] = o;
        }
    }
    __syncthreads();
    const int row = row0 + w;
    const float* vr = v_s[w];
    float a0 = 0.f, a1 = 0.f, a2 = 0.f, a3 = 0.f;
    const int c0 = lane, c1 = lane + 32, c2 = lane + 64;
#pragma unroll 8
    for (int k = 0; k < 512; k++) {
        float v = vr[k];
        const float* wr = Wc + (size_t)k * 97;
        a0 = fmaf(v, wr[c0], a0);
        a1 = fmaf(v, wr[c1], a1);
        a2 = fmaf(v, wr[c2], a2);
        if (lane == 0) a3 = fmaf(v, wr[96], a3);
    }
    float* orow = out + (size_t)row * 97;
    orow[c0] = a0 + Wcb[c0];
    orow[c1] = a1 + Wcb[c1];
    orow[c2] = a2 + Wcb[c2];
    if (lane == 0) orow[96] = a3 + Wcb[96];
}

extern "C" void kernel_launch(void* const* d_in, const int* in_sizes, int n_in,
                              void* d_out, int out_size) {
    const float* inp  = (const float*)d_in[0];
    const float* emb  = (const float*)d_in[1];
    const float* Wo_w = (const float*)d_in[2];
    const float* Wo_b = (const float*)d_in[3];
    const float* Wv_w = (const float*)d_in[4];
    const float* Wv_b = (const float*)d_in[5];
    const float* We_w = (const float*)d_in[6];
    const float* Wc_w = (const float*)d_in[8];
    const float* Wc_b = (const float*)d_in[9];
    float* out = (float*)d_out;
    float* vf = out;                         // (32*32, 512)
    float* logits = out + 32 * 32 * 512;     // (32*32, 97)

    k0_nop<<<1, 32>>>();                               // keep k23 in ncu's 4th slot
    k1a_wo<<<dim3(4, 32), 128>>>(emb, Wo_w);
    k1b_wo<<<16, 256>>>(Wo_b);
    k23_gemm_tanh<<<dim3(4, 128), 256>>>(inp, Wv_w, Wv_b, We_w);
    k4_softmax<<<32, 512>>>();
    k5a_vf<<<dim3(32, 4, 8), 128>>>(inp);
    k6_logits<<<128, 256>>>(Wc_w, Wc_b, vf, logits);
}